// round 11
// baseline (speedup 1.0000x reference)
#include <cuda_runtime.h>
#include <cuda_fp16.h>
#include <cstdint>

#define M_DIM 4096
#define K_DIM 4096
#define N_DIM 4096
#define NV4_N 2048
#define FP8_N 1024

#define BM 128
#define BN 256
#define BK 64
#define STAGES 4
#define NITER (K_DIM / BK)     // 64
#define NTHREADS 256

// ---- scratch (device globals: allowed) ----
__device__ __half g_Wh[(size_t)N_DIM * K_DIM];   // 32 MB dequantized+permuted W (fp16)
__device__ __half g_Xh[(size_t)M_DIM * K_DIM];   // 32 MB fp16 X
__device__ int    g_perm[N_DIM];

__constant__ float c_code[16] = {0.f, 0.5f, 1.f, 1.5f, 2.f, 3.f, 4.f, 6.f,
                                 -0.f, -0.5f, -1.f, -1.5f, -2.f, -3.f, -4.f, -6.f};

// ================= helpers =================
__device__ __forceinline__ uint32_t smem_u32(const void* p) {
    uint32_t a;
    asm("{ .reg .u64 t; cvta.to.shared.u64 t, %1; cvt.u32.u64 %0, t; }" : "=r"(a) : "l"(p));
    return a;
}
#define CP_ASYNC16(dst, src) \
    asm volatile("cp.async.cg.shared.global [%0], [%1], 16;" :: "r"(dst), "l"(src) : "memory")
#define CP_COMMIT() asm volatile("cp.async.commit_group;" ::: "memory")
#define CP_WAIT2()  asm volatile("cp.async.wait_group 2;" ::: "memory")
#define CP_WAIT1()  asm volatile("cp.async.wait_group 1;" ::: "memory")
#define CP_WAIT0()  asm volatile("cp.async.wait_group 0;" ::: "memory")

#define LDSM_X4(r0, r1, r2, r3, addr) \
    asm volatile("ldmatrix.sync.aligned.m8n8.x4.shared.b16 {%0,%1,%2,%3}, [%4];" \
                 : "=r"(r0), "=r"(r1), "=r"(r2), "=r"(r3) : "r"(addr))

#define MMA16816(c, a, b) \
    asm volatile("mma.sync.aligned.m16n8k16.row.col.f32.f16.f16.f32 " \
                 "{%0,%1,%2,%3}, {%4,%5,%6,%7}, {%8,%9}, {%0,%1,%2,%3};" \
                 : "+f"((c)[0]), "+f"((c)[1]), "+f"((c)[2]), "+f"((c)[3]) \
                 : "r"((a)[0]), "r"((a)[1]), "r"((a)[2]), "r"((a)[3]), \
                   "r"((b)[0]), "r"((b)[1]))

// streaming store (don't pollute L2 with output; operands stay resident)
__device__ __forceinline__ void stcs_f2(float* p, float2 v) {
    asm volatile("st.global.cs.v2.f32 [%0], {%1, %2};" :: "l"(p), "f"(v.x), "f"(v.y) : "memory");
}

#define SW128(off) ((off) ^ (((off) >> 3) & 0x70))

// SMEM: A stages 16KB each (128 rows x 128B), B stages 32KB each (256 rows x 128B)
#define SM_A(s)  ((s) * 16384)
#define SM_B(s)  (65536 + (s) * 32768)
#define SMEM_TOTAL (65536 + STAGES * 32768)   // 196608 = 192KB, 1 CTA/SM

// ================= pre-kernels =================
__global__ void perm_canon_kernel(const void* __restrict__ perm_raw)
{
    __shared__ int s_bad;
    const int tid = threadIdx.x;
    if (tid == 0) s_bad = 0;
    __syncthreads();
    const long long* p64 = (const long long*)perm_raw;
    for (int i = tid; i < 2048; i += blockDim.x) {
        long long v = p64[i];
        if (v < 0 || v >= N_DIM) atomicOr(&s_bad, 1);
    }
    __syncthreads();
    if (s_bad) { const int* p32 = (const int*)perm_raw;
        for (int i = tid; i < N_DIM; i += blockDim.x) g_perm[i] = p32[i];
    } else {
        for (int i = tid; i < N_DIM; i += blockDim.x) g_perm[i] = (int)p64[i];
    }
}

// fused: blocks [0, 2048) convert X; blocks [2048, 6144) dequant W row (blk-2048)
#define XCONV_BLOCKS 2048
__global__ void prep_kernel(const float* __restrict__ X,
                            const int* __restrict__ nvfp4_idx,
                            const float* __restrict__ nvfp4_scales,
                            const float* __restrict__ gscale_p,
                            const float* __restrict__ w_fp8,
                            const float* __restrict__ fp8_scale_p,
                            const float* __restrict__ w_fp16)
{
    const int tid = threadIdx.x;
    if (blockIdx.x < XCONV_BLOCKS) {
        size_t base = ((size_t)blockIdx.x * 256 + tid) * 8;
        const size_t stride = (size_t)XCONV_BLOCKS * 256 * 8;
        #pragma unroll
        for (int r = 0; r < 4; r++, base += stride) {
            float4 a = *(const float4*)(X + base);
            float4 b = *(const float4*)(X + base + 4);
            __half2 h[4];
            h[0] = __floats2half2_rn(a.x, a.y);
            h[1] = __floats2half2_rn(a.z, a.w);
            h[2] = __floats2half2_rn(b.x, b.y);
            h[3] = __floats2half2_rn(b.z, b.w);
            *(uint4*)(g_Xh + base) = *(uint4*)h;
        }
        return;
    }
    const int j = blockIdx.x - XCONV_BLOCKS;
    const int g = g_perm[j];
    __half* __restrict__ dst = &g_Wh[(size_t)j * K_DIM];

    if (g < NV4_N) {
        const float gs = gscale_p[0];
        const int* __restrict__ idx = nvfp4_idx + (size_t)g * K_DIM;
        const float* __restrict__ sc = nvfp4_scales + (size_t)g * (K_DIM / 16);
        const int k = tid * 16;   // 256 threads x 16 = 4096
        const float s = sc[k >> 4] * gs;
        #pragma unroll
        for (int c = 0; c < 16; c += 8) {
            int4 i0 = *(const int4*)&idx[k + c];
            int4 i1 = *(const int4*)&idx[k + c + 4];
            __half2 h[4];
            h[0] = __floats2half2_rn(c_code[i0.x & 15] * s, c_code[i0.y & 15] * s);
            h[1] = __floats2half2_rn(c_code[i0.z & 15] * s, c_code[i0.w & 15] * s);
            h[2] = __floats2half2_rn(c_code[i1.x & 15] * s, c_code[i1.y & 15] * s);
            h[3] = __floats2half2_rn(c_code[i1.z & 15] * s, c_code[i1.w & 15] * s);
            *(uint4*)&dst[k + c] = *(uint4*)h;
        }
    } else {
        const bool is8 = (g < NV4_N + FP8_N);
        const float fs = is8 ? fp8_scale_p[0] : 1.f;
        const float* __restrict__ w = is8 ? (w_fp8 + (size_t)(g - NV4_N) * K_DIM)
                                          : (w_fp16 + (size_t)(g - NV4_N - FP8_N) * K_DIM);
        for (int k = tid * 8; k < K_DIM; k += 256 * 8) {
            float4 a = *(const float4*)&w[k];
            float4 b = *(const float4*)&w[k + 4];
            __half2 h[4];
            h[0] = __floats2half2_rn(a.x * fs, a.y * fs);
            h[1] = __floats2half2_rn(a.z * fs, a.w * fs);
            h[2] = __floats2half2_rn(b.x * fs, b.y * fs);
            h[3] = __floats2half2_rn(b.z * fs, b.w * fs);
            *(uint4*)&dst[k] = *(uint4*)h;
        }
    }
}

// ====== HMMA GEMM (CUTLASS-canonical: 128x256, 256 thr, warp 64x64, 4 stages) ======
__device__ __forceinline__ void load_stage(uint32_t smem_base, int s, int it, int m0, int n0)
{
    const int tid = threadIdx.x;
    const int k0 = it * BK;
    const uint32_t a_base = smem_base + SM_A(s);
    const uint32_t b_base = smem_base + SM_B(s);
    // A: 128 rows x 8 x 16B = 1024 granules, 4 per thread
    #pragma unroll
    for (int i = 0; i < 4; i++) {
        int gr = tid + i * NTHREADS;
        int row = gr >> 3, c16 = gr & 7;
        const __half* src = g_Xh + (size_t)(m0 + row) * K_DIM + k0 + c16 * 8;
        uint32_t off = row * 128 + c16 * 16;
        CP_ASYNC16(a_base + SW128(off), src);
    }
    // B: 256 rows x 8 x 16B = 2048 granules, 8 per thread
    #pragma unroll
    for (int i = 0; i < 8; i++) {
        int gr = tid + i * NTHREADS;
        int row = gr >> 3, c16 = gr & 7;
        const __half* src = g_Wh + (size_t)(n0 + row) * K_DIM + k0 + c16 * 8;
        uint32_t off = row * 128 + c16 * 16;
        CP_ASYNC16(b_base + SW128(off), src);
    }
}

__global__ __launch_bounds__(NTHREADS, 1)
void gemm_hmma_kernel(const float* __restrict__ bias, float* __restrict__ out)
{
    extern __shared__ char smem[];
    const uint32_t smem_base = smem_u32(smem);
    const int tid  = threadIdx.x;
    const int wid  = tid >> 5, lane = tid & 31;
    const int wm   = wid & 1;            // 2 warps along M (64 rows each)
    const int wn   = wid >> 1;           // 4 warps along N (64 cols each)
    const int m0   = blockIdx.y * BM;
    const int n0   = blockIdx.x * BN;

    float acc[4][8][4] = {};             // 128 regs (fits: 256 regs/thread at 1 CTA)

    const int a_row_b = (lane & 15);
    const int a_kh  = (lane >> 4) * 8;
    const int b_row_b = (lane >> 4) * 8 + (lane & 7);
    const int b_kh  = ((lane >> 3) & 1) * 8;

    #pragma unroll
    for (int s = 0; s < STAGES - 1; s++) { load_stage(smem_base, s, s, m0, n0); CP_COMMIT(); }

    for (int it = 0; it < NITER; it++) {
        const int s = it % STAGES;
        const int rem = NITER - 1 - it;
        if (rem >= 2)      CP_WAIT2();
        else if (rem == 1) CP_WAIT1();
        else               CP_WAIT0();
        __syncthreads();

        const int nxt = it + STAGES - 1;
        if (nxt < NITER) { load_stage(smem_base, nxt % STAGES, nxt, m0, n0); CP_COMMIT(); }

        const uint32_t a_base = smem_base + SM_A(s);
        const uint32_t b_base = smem_base + SM_B(s);

        #pragma unroll
        for (int kk = 0; kk < 4; kk++) {          // 4 x k16 per BK=64
            const int k0 = kk * 16;
            uint32_t af[4][4];
            #pragma unroll
            for (int mt = 0; mt < 4; mt++) {
                uint32_t off = (wm * 64 + mt * 16 + a_row_b) * 128 + (k0 + a_kh) * 2;
                LDSM_X4(af[mt][0], af[mt][1], af[mt][2], af[mt][3],
                        a_base + SW128(off));
            }
            uint32_t bf[8][2];
            #pragma unroll
            for (int p = 0; p < 4; p++) {
                uint32_t off = (wn * 64 + p * 16 + b_row_b) * 128 + (k0 + b_kh) * 2;
                LDSM_X4(bf[2 * p][0], bf[2 * p][1], bf[2 * p + 1][0], bf[2 * p + 1][1],
                        b_base + SW128(off));
            }
            #pragma unroll
            for (int mt = 0; mt < 4; mt++)
                #pragma unroll
                for (int nt = 0; nt < 8; nt++)
                    MMA16816(acc[mt][nt], af[mt], bf[nt]);
        }
    }

    // epilogue: streaming stores
    const int er = lane >> 2;
    const int ec = (lane & 3) * 2;
    #pragma unroll
    for (int nt = 0; nt < 8; nt++) {
        const int n = n0 + wn * 64 + nt * 8 + ec;
        const float2 bv = *(const float2*)(bias + n);
        #pragma unroll
        for (int mt = 0; mt < 4; mt++) {
            const int m = m0 + wm * 64 + mt * 16 + er;
            float2 v0 = { acc[mt][nt][0] + bv.x, acc[mt][nt][1] + bv.y };
            float2 v1 = { acc[mt][nt][2] + bv.x, acc[mt][nt][3] + bv.y };
            stcs_f2(out + (size_t)m * N_DIM + n, v0);
            stcs_f2(out + (size_t)(m + 8) * N_DIM + n, v1);
        }
    }
}

// ================= launch =================
extern "C" void kernel_launch(void* const* d_in, const int* in_sizes, int n_in,
                              void* d_out, int out_size)
{
    const float* x            = (const float*)d_in[0];
    const int*   nvfp4_idx    = (const int*)d_in[1];
    const float* nvfp4_scales = (const float*)d_in[2];
    const float* nvfp4_gscale = (const float*)d_in[3];
    const float* w_fp8        = (const float*)d_in[4];
    const float* fp8_scale    = (const float*)d_in[5];
    const float* w_fp16       = (const float*)d_in[6];
    const float* bias         = (const float*)d_in[7];
    const void*  inv_perm     = (const void*)d_in[8];
    float*       out          = (float*)d_out;

    cudaFuncSetAttribute(gemm_hmma_kernel, cudaFuncAttributeMaxDynamicSharedMemorySize, SMEM_TOTAL);

    perm_canon_kernel<<<1, 256>>>(inv_perm);
    prep_kernel<<<XCONV_BLOCKS + N_DIM, 256>>>(x, nvfp4_idx, nvfp4_scales, nvfp4_gscale,
                                               w_fp8, fp8_scale, w_fp16);

    dim3 grid(N_DIM / BN, M_DIM / BM);   // (16, 32)
    gemm_hmma_kernel<<<grid, NTHREADS, SMEM_TOTAL>>>(bias, out);
}

// round 12
// speedup vs baseline: 1.0862x; 1.0862x over previous
#include <cuda_runtime.h>
#include <cuda_fp16.h>
#include <cstdint>

#define M_DIM 4096
#define K_DIM 4096
#define N_DIM 4096
#define NV4_N 2048
#define FP8_N 1024

#define BM 128
#define BN 128
#define BK 64
#define STAGES 3
#define NITER (K_DIM / BK)     // 64
#define NTHREADS 128           // 4 fat warps (64x64 each), 2 CTAs/SM

// ---- scratch (device globals: allowed) ----
__device__ __half g_Wh[(size_t)N_DIM * K_DIM];   // 32 MB dequantized+permuted W (fp16)
__device__ __half g_Xh[(size_t)M_DIM * K_DIM];   // 32 MB fp16 X

__constant__ float c_code[16] = {0.f, 0.5f, 1.f, 1.5f, 2.f, 3.f, 4.f, 6.f,
                                 -0.f, -0.5f, -1.f, -1.5f, -2.f, -3.f, -4.f, -6.f};

// ================= helpers =================
__device__ __forceinline__ uint32_t smem_u32(const void* p) {
    uint32_t a;
    asm("{ .reg .u64 t; cvta.to.shared.u64 t, %1; cvt.u32.u64 %0, t; }" : "=r"(a) : "l"(p));
    return a;
}
#define CP_ASYNC16(dst, src) \
    asm volatile("cp.async.cg.shared.global [%0], [%1], 16;" :: "r"(dst), "l"(src) : "memory")
#define CP_COMMIT() asm volatile("cp.async.commit_group;" ::: "memory")
#define CP_WAIT1()  asm volatile("cp.async.wait_group 1;" ::: "memory")
#define CP_WAIT0()  asm volatile("cp.async.wait_group 0;" ::: "memory")

#define LDSM_X4(r0, r1, r2, r3, addr) \
    asm volatile("ldmatrix.sync.aligned.m8n8.x4.shared.b16 {%0,%1,%2,%3}, [%4];" \
                 : "=r"(r0), "=r"(r1), "=r"(r2), "=r"(r3) : "r"(addr))

#define MMA16816(c, a, b) \
    asm volatile("mma.sync.aligned.m16n8k16.row.col.f32.f16.f16.f32 " \
                 "{%0,%1,%2,%3}, {%4,%5,%6,%7}, {%8,%9}, {%0,%1,%2,%3};" \
                 : "+f"((c)[0]), "+f"((c)[1]), "+f"((c)[2]), "+f"((c)[3]) \
                 : "r"((a)[0]), "r"((a)[1]), "r"((a)[2]), "r"((a)[3]), \
                   "r"((b)[0]), "r"((b)[1]))

__device__ __forceinline__ void stcs_f2(float* p, float2 v) {
    asm volatile("st.global.cs.v2.f32 [%0], {%1, %2};" :: "l"(p), "f"(v.x), "f"(v.y) : "memory");
}

#define SW128(off) ((off) ^ (((off) >> 3) & 0x70))

// SMEM per CTA: A stages 16KB each (128 rows x 128B), B stages 16KB each
#define SM_A(s)  ((s) * 16384)
#define SM_B(s)  (49152 + (s) * 16384)
#define SMEM_TOTAL 98304   // 96KB -> 2 CTAs/SM

// ================= prep (X convert + W dequant, perm dtype probe inlined) =================
// dtype probe: for int32 data misread as int64, p64[i] = perm32[2i] + perm32[2i+1]*2^32.
// A permutation of [0,4096) has exactly one 0, so perm32[1] and perm32[3] cannot both be 0
// -> at least one of p64[0], p64[1] is out of range. Genuine int64 perm: both in range.
__device__ __forceinline__ int perm_at(const void* perm_raw, int j) {
    const long long* p64 = (const long long*)perm_raw;
    const bool is64 = ((unsigned long long)p64[0] < (unsigned long long)N_DIM) &&
                      ((unsigned long long)p64[1] < (unsigned long long)N_DIM);
    return is64 ? (int)p64[j] : ((const int*)perm_raw)[j];
}

#define XCONV_BLOCKS 2048
__global__ void prep_kernel(const float* __restrict__ X,
                            const int* __restrict__ nvfp4_idx,
                            const float* __restrict__ nvfp4_scales,
                            const float* __restrict__ gscale_p,
                            const float* __restrict__ w_fp8,
                            const float* __restrict__ fp8_scale_p,
                            const float* __restrict__ w_fp16,
                            const void* __restrict__ perm_raw)
{
    const int tid = threadIdx.x;
    if (blockIdx.x < XCONV_BLOCKS) {
        size_t base = ((size_t)blockIdx.x * 256 + tid) * 8;
        const size_t stride = (size_t)XCONV_BLOCKS * 256 * 8;
        #pragma unroll
        for (int r = 0; r < 4; r++, base += stride) {
            float4 a = *(const float4*)(X + base);
            float4 b = *(const float4*)(X + base + 4);
            __half2 h[4];
            h[0] = __floats2half2_rn(a.x, a.y);
            h[1] = __floats2half2_rn(a.z, a.w);
            h[2] = __floats2half2_rn(b.x, b.y);
            h[3] = __floats2half2_rn(b.z, b.w);
            *(uint4*)(g_Xh + base) = *(uint4*)h;
        }
        return;
    }
    const int j = blockIdx.x - XCONV_BLOCKS;
    const int g = perm_at(perm_raw, j);
    __half* __restrict__ dst = &g_Wh[(size_t)j * K_DIM];

    if (g < NV4_N) {
        const float gs = gscale_p[0];
        const int* __restrict__ idx = nvfp4_idx + (size_t)g * K_DIM;
        const float* __restrict__ sc = nvfp4_scales + (size_t)g * (K_DIM / 16);
        const int k = tid * 16;   // 256 threads x 16 = 4096
        const float s = sc[k >> 4] * gs;
        #pragma unroll
        for (int c = 0; c < 16; c += 8) {
            int4 i0 = *(const int4*)&idx[k + c];
            int4 i1 = *(const int4*)&idx[k + c + 4];
            __half2 h[4];
            h[0] = __floats2half2_rn(c_code[i0.x & 15] * s, c_code[i0.y & 15] * s);
            h[1] = __floats2half2_rn(c_code[i0.z & 15] * s, c_code[i0.w & 15] * s);
            h[2] = __floats2half2_rn(c_code[i1.x & 15] * s, c_code[i1.y & 15] * s);
            h[3] = __floats2half2_rn(c_code[i1.z & 15] * s, c_code[i1.w & 15] * s);
            *(uint4*)&dst[k + c] = *(uint4*)h;
        }
    } else {
        const bool is8 = (g < NV4_N + FP8_N);
        const float fs = is8 ? fp8_scale_p[0] : 1.f;
        const float* __restrict__ w = is8 ? (w_fp8 + (size_t)(g - NV4_N) * K_DIM)
                                          : (w_fp16 + (size_t)(g - NV4_N - FP8_N) * K_DIM);
        for (int k = tid * 8; k < K_DIM; k += 256 * 8) {
            float4 a = *(const float4*)&w[k];
            float4 b = *(const float4*)&w[k + 4];
            __half2 h[4];
            h[0] = __floats2half2_rn(a.x * fs, a.y * fs);
            h[1] = __floats2half2_rn(a.z * fs, a.w * fs);
            h[2] = __floats2half2_rn(b.x * fs, b.y * fs);
            h[3] = __floats2half2_rn(b.z * fs, b.w * fs);
            *(uint4*)&dst[k] = *(uint4*)h;
        }
    }
}

// ===== HMMA GEMM (128x128, 128 thr, 4 fat warps 2Mx2N of 64x64, 2 CTAs/SM) =====
__device__ __forceinline__ void load_stage(uint32_t smem_base, int s, int it, int m0, int n0)
{
    const int tid = threadIdx.x;
    const int k0 = it * BK;
    const uint32_t a_base = smem_base + SM_A(s);
    const uint32_t b_base = smem_base + SM_B(s);
    // A: 128 rows x 8 x 16B = 1024 granules, 8 per thread
    #pragma unroll
    for (int i = 0; i < 8; i++) {
        int gr = tid + i * NTHREADS;
        int row = gr >> 3, c16 = gr & 7;
        const __half* src = g_Xh + (size_t)(m0 + row) * K_DIM + k0 + c16 * 8;
        uint32_t off = row * 128 + c16 * 16;
        CP_ASYNC16(a_base + SW128(off), src);
    }
    // B: 128 rows x 8 x 16B = 1024 granules, 8 per thread
    #pragma unroll
    for (int i = 0; i < 8; i++) {
        int gr = tid + i * NTHREADS;
        int row = gr >> 3, c16 = gr & 7;
        const __half* src = g_Wh + (size_t)(n0 + row) * K_DIM + k0 + c16 * 8;
        uint32_t off = row * 128 + c16 * 16;
        CP_ASYNC16(b_base + SW128(off), src);
    }
}

__global__ __launch_bounds__(NTHREADS, 2)
void gemm_hmma_kernel(const float* __restrict__ bias, float* __restrict__ out)
{
    extern __shared__ char smem[];
    const uint32_t smem_base = smem_u32(smem);
    const int tid  = threadIdx.x;
    const int wid  = tid >> 5, lane = tid & 31;
    const int wm   = wid & 1;            // 2 warps along M (64 rows each)
    const int wn   = wid >> 1;           // 2 warps along N (64 cols each)
    const int m0   = blockIdx.y * BM;
    const int n0   = blockIdx.x * BN;

    float acc[4][8][4] = {};             // 128 regs; budget 64K/128thr -> up to 255, no spill

    const int a_row_b = (lane & 15);
    const int a_kh  = (lane >> 4) * 8;
    const int b_row_b = (lane >> 4) * 8 + (lane & 7);
    const int b_kh  = ((lane >> 3) & 1) * 8;

    #pragma unroll
    for (int s = 0; s < STAGES - 1; s++) { load_stage(smem_base, s, s, m0, n0); CP_COMMIT(); }

    for (int it = 0; it < NITER; it++) {
        const int s = it % STAGES;
        if (it == NITER - 1) CP_WAIT0(); else CP_WAIT1();
        __syncthreads();

        const int nxt = it + STAGES - 1;
        if (nxt < NITER) { load_stage(smem_base, nxt % STAGES, nxt, m0, n0); CP_COMMIT(); }

        const uint32_t a_base = smem_base + SM_A(s);
        const uint32_t b_base = smem_base + SM_B(s);

        #pragma unroll
        for (int kk = 0; kk < 4; kk++) {          // 4 x k16 per BK=64
            const int k0 = kk * 16;
            uint32_t af[4][4];
            #pragma unroll
            for (int mt = 0; mt < 4; mt++) {
                uint32_t off = (wm * 64 + mt * 16 + a_row_b) * 128 + (k0 + a_kh) * 2;
                LDSM_X4(af[mt][0], af[mt][1], af[mt][2], af[mt][3],
                        a_base + SW128(off));
            }
            uint32_t bf[8][2];
            #pragma unroll
            for (int p = 0; p < 4; p++) {
                uint32_t off = (wn * 64 + p * 16 + b_row_b) * 128 + (k0 + b_kh) * 2;
                LDSM_X4(bf[2 * p][0], bf[2 * p][1], bf[2 * p + 1][0], bf[2 * p + 1][1],
                        b_base + SW128(off));
            }
            #pragma unroll
            for (int mt = 0; mt < 4; mt++)
                #pragma unroll
                for (int nt = 0; nt < 8; nt++)
                    MMA16816(acc[mt][nt], af[mt], bf[nt]);
        }
    }

    // epilogue: streaming stores
    const int er = lane >> 2;
    const int ec = (lane & 3) * 2;
    #pragma unroll
    for (int nt = 0; nt < 8; nt++) {
        const int n = n0 + wn * 64 + nt * 8 + ec;
        const float2 bv = *(const float2*)(bias + n);
        #pragma unroll
        for (int mt = 0; mt < 4; mt++) {
            const int m = m0 + wm * 64 + mt * 16 + er;
            float2 v0 = { acc[mt][nt][0] + bv.x, acc[mt][nt][1] + bv.y };
            float2 v1 = { acc[mt][nt][2] + bv.x, acc[mt][nt][3] + bv.y };
            stcs_f2(out + (size_t)m * N_DIM + n, v0);
            stcs_f2(out + (size_t)(m + 8) * N_DIM + n, v1);
        }
    }
}

// ================= launch =================
extern "C" void kernel_launch(void* const* d_in, const int* in_sizes, int n_in,
                              void* d_out, int out_size)
{
    const float* x            = (const float*)d_in[0];
    const int*   nvfp4_idx    = (const int*)d_in[1];
    const float* nvfp4_scales = (const float*)d_in[2];
    const float* nvfp4_gscale = (const float*)d_in[3];
    const float* w_fp8        = (const float*)d_in[4];
    const float* fp8_scale    = (const float*)d_in[5];
    const float* w_fp16       = (const float*)d_in[6];
    const float* bias         = (const float*)d_in[7];
    const void*  inv_perm     = (const void*)d_in[8];
    float*       out          = (float*)d_out;

    cudaFuncSetAttribute(gemm_hmma_kernel, cudaFuncAttributeMaxDynamicSharedMemorySize, SMEM_TOTAL);

    prep_kernel<<<XCONV_BLOCKS + N_DIM, 256>>>(x, nvfp4_idx, nvfp4_scales, nvfp4_gscale,
                                               w_fp8, fp8_scale, w_fp16, inv_perm);

    dim3 grid(N_DIM / BN, M_DIM / BM);   // (32, 32)
    gemm_hmma_kernel<<<grid, NTHREADS, SMEM_TOTAL>>>(bias, out);
}

// round 13
// speedup vs baseline: 1.1347x; 1.0446x over previous
#include <cuda_runtime.h>
#include <cuda_fp16.h>
#include <cstdint>

#define M_DIM 4096
#define K_DIM 4096
#define N_DIM 4096
#define NV4_N 2048
#define FP8_N 1024

#define BM 128
#define BN 128
#define BK 64
#define STAGES 3
#define NITER (K_DIM / BK)     // 64
#define NTHREADS 256

// ---- scratch (device globals: allowed) ----
__device__ __half g_Wh[(size_t)N_DIM * K_DIM];   // 32 MB dequantized+permuted W (fp16)
__device__ __half g_Xh[(size_t)M_DIM * K_DIM];   // 32 MB fp16 X

__constant__ float c_code[16] = {0.f, 0.5f, 1.f, 1.5f, 2.f, 3.f, 4.f, 6.f,
                                 -0.f, -0.5f, -1.f, -1.5f, -2.f, -3.f, -4.f, -6.f};

// ================= helpers =================
__device__ __forceinline__ uint32_t smem_u32(const void* p) {
    uint32_t a;
    asm("{ .reg .u64 t; cvta.to.shared.u64 t, %1; cvt.u32.u64 %0, t; }" : "=r"(a) : "l"(p));
    return a;
}
#define CP_ASYNC16(dst, src) \
    asm volatile("cp.async.cg.shared.global [%0], [%1], 16;" :: "r"(dst), "l"(src) : "memory")
#define CP_COMMIT() asm volatile("cp.async.commit_group;" ::: "memory")
#define CP_WAIT1()  asm volatile("cp.async.wait_group 1;" ::: "memory")
#define CP_WAIT0()  asm volatile("cp.async.wait_group 0;" ::: "memory")

#define LDSM_X4(r0, r1, r2, r3, addr) \
    asm volatile("ldmatrix.sync.aligned.m8n8.x4.shared.b16 {%0,%1,%2,%3}, [%4];" \
                 : "=r"(r0), "=r"(r1), "=r"(r2), "=r"(r3) : "r"(addr))

#define MMA16816(c, a, b) \
    asm volatile("mma.sync.aligned.m16n8k16.row.col.f32.f16.f16.f32 " \
                 "{%0,%1,%2,%3}, {%4,%5,%6,%7}, {%8,%9}, {%0,%1,%2,%3};" \
                 : "+f"((c)[0]), "+f"((c)[1]), "+f"((c)[2]), "+f"((c)[3]) \
                 : "r"((a)[0]), "r"((a)[1]), "r"((a)[2]), "r"((a)[3]), \
                   "r"((b)[0]), "r"((b)[1]))

// streaming store (output is write-once; keep L2 for operands)
__device__ __forceinline__ void stcs_f2(float* p, float2 v) {
    asm volatile("st.global.cs.v2.f32 [%0], {%1, %2};" :: "l"(p), "f"(v.x), "f"(v.y) : "memory");
}

#define SW128(off) ((off) ^ (((off) >> 3) & 0x70))

// SMEM per CTA: A stages 16KB each (128 rows x 128B), B stages 16KB each
#define SM_A(s)  ((s) * 16384)
#define SM_B(s)  (49152 + (s) * 16384)
#define SMEM_TOTAL 98304   // 96KB -> 2 CTAs/SM

// ================= prep (X convert + W dequant, perm dtype probe inlined) =================
// dtype probe (validated R12): int32 data misread as int64 gives p64[i] = lo + hi*2^32.
// A permutation of [0,4096) contains exactly one 0, so the int32 elements at odd
// positions 1 and 3 cannot both be 0 -> at least one of p64[0], p64[1] overflows the
// valid range. A genuine int64 permutation has both in range.
__device__ __forceinline__ int perm_at(const void* perm_raw, int j) {
    const long long* p64 = (const long long*)perm_raw;
    const bool is64 = ((unsigned long long)p64[0] < (unsigned long long)N_DIM) &&
                      ((unsigned long long)p64[1] < (unsigned long long)N_DIM);
    return is64 ? (int)p64[j] : ((const int*)perm_raw)[j];
}

#define XCONV_BLOCKS 2048
__global__ void prep_kernel(const float* __restrict__ X,
                            const int* __restrict__ nvfp4_idx,
                            const float* __restrict__ nvfp4_scales,
                            const float* __restrict__ gscale_p,
                            const float* __restrict__ w_fp8,
                            const float* __restrict__ fp8_scale_p,
                            const float* __restrict__ w_fp16,
                            const void* __restrict__ perm_raw)
{
    const int tid = threadIdx.x;
    if (blockIdx.x < XCONV_BLOCKS) {
        size_t base = ((size_t)blockIdx.x * 256 + tid) * 8;
        const size_t stride = (size_t)XCONV_BLOCKS * 256 * 8;
        #pragma unroll
        for (int r = 0; r < 4; r++, base += stride) {
            float4 a = *(const float4*)(X + base);
            float4 b = *(const float4*)(X + base + 4);
            __half2 h[4];
            h[0] = __floats2half2_rn(a.x, a.y);
            h[1] = __floats2half2_rn(a.z, a.w);
            h[2] = __floats2half2_rn(b.x, b.y);
            h[3] = __floats2half2_rn(b.z, b.w);
            *(uint4*)(g_Xh + base) = *(uint4*)h;
        }
        return;
    }
    const int j = blockIdx.x - XCONV_BLOCKS;
    const int g = perm_at(perm_raw, j);
    __half* __restrict__ dst = &g_Wh[(size_t)j * K_DIM];

    if (g < NV4_N) {
        const float gs = gscale_p[0];
        const int* __restrict__ idx = nvfp4_idx + (size_t)g * K_DIM;
        const float* __restrict__ sc = nvfp4_scales + (size_t)g * (K_DIM / 16);
        const int k = tid * 16;   // 256 threads x 16 = 4096 = K
        const float s = sc[k >> 4] * gs;
        #pragma unroll
        for (int c = 0; c < 16; c += 8) {
            int4 i0 = *(const int4*)&idx[k + c];
            int4 i1 = *(const int4*)&idx[k + c + 4];
            __half2 h[4];
            h[0] = __floats2half2_rn(c_code[i0.x & 15] * s, c_code[i0.y & 15] * s);
            h[1] = __floats2half2_rn(c_code[i0.z & 15] * s, c_code[i0.w & 15] * s);
            h[2] = __floats2half2_rn(c_code[i1.x & 15] * s, c_code[i1.y & 15] * s);
            h[3] = __floats2half2_rn(c_code[i1.z & 15] * s, c_code[i1.w & 15] * s);
            *(uint4*)&dst[k + c] = *(uint4*)h;
        }
    } else {
        const bool is8 = (g < NV4_N + FP8_N);
        const float fs = is8 ? fp8_scale_p[0] : 1.f;
        const float* __restrict__ w = is8 ? (w_fp8 + (size_t)(g - NV4_N) * K_DIM)
                                          : (w_fp16 + (size_t)(g - NV4_N - FP8_N) * K_DIM);
        for (int k = tid * 8; k < K_DIM; k += 256 * 8) {
            float4 a = *(const float4*)&w[k];
            float4 b = *(const float4*)&w[k + 4];
            __half2 h[4];
            h[0] = __floats2half2_rn(a.x * fs, a.y * fs);
            h[1] = __floats2half2_rn(a.z * fs, a.w * fs);
            h[2] = __floats2half2_rn(b.x * fs, b.y * fs);
            h[3] = __floats2half2_rn(b.z * fs, b.w * fs);
            *(uint4*)&dst[k] = *(uint4*)h;
        }
    }
}

// ===== HMMA GEMM (R7 structural optimum: 128x128, 256 thr, 8 warps 4Mx2N, 2 CTAs/SM) =====
__device__ __forceinline__ void load_stage(uint32_t smem_base, int s, int it, int m0, int n0)
{
    const int tid = threadIdx.x;
    const int k0 = it * BK;
    const uint32_t a_base = smem_base + SM_A(s);
    const uint32_t b_base = smem_base + SM_B(s);
    #pragma unroll
    for (int i = 0; i < 4; i++) {
        int gr = tid + i * NTHREADS;
        int row = gr >> 3, c16 = gr & 7;
        const __half* src = g_Xh + (size_t)(m0 + row) * K_DIM + k0 + c16 * 8;
        uint32_t off = row * 128 + c16 * 16;
        CP_ASYNC16(a_base + SW128(off), src);
    }
    #pragma unroll
    for (int i = 0; i < 4; i++) {
        int gr = tid + i * NTHREADS;
        int row = gr >> 3, c16 = gr & 7;
        const __half* src = g_Wh + (size_t)(n0 + row) * K_DIM + k0 + c16 * 8;
        uint32_t off = row * 128 + c16 * 16;
        CP_ASYNC16(b_base + SW128(off), src);
    }
}

__global__ __launch_bounds__(NTHREADS, 2)
void gemm_hmma_kernel(const float* __restrict__ bias, float* __restrict__ out)
{
    extern __shared__ char smem[];
    const uint32_t smem_base = smem_u32(smem);
    const int tid  = threadIdx.x;
    const int wid  = tid >> 5, lane = tid & 31;
    const int wm   = wid & 3;            // 4 warps along M (32 rows each)
    const int wn   = wid >> 2;           // 2 warps along N (64 cols each)
    const int m0   = blockIdx.y * BM;
    const int n0   = blockIdx.x * BN;

    float acc[2][8][4] = {};             // 64 regs

    const int a_row_b = (lane & 15);
    const int a_kh  = (lane >> 4) * 8;
    const int b_row_b = (lane >> 4) * 8 + (lane & 7);
    const int b_kh  = ((lane >> 3) & 1) * 8;

    #pragma unroll
    for (int s = 0; s < STAGES - 1; s++) { load_stage(smem_base, s, s, m0, n0); CP_COMMIT(); }

    for (int it = 0; it < NITER; it++) {
        const int s = it % STAGES;
        if (it == NITER - 1) CP_WAIT0(); else CP_WAIT1();
        __syncthreads();

        const int nxt = it + STAGES - 1;
        if (nxt < NITER) { load_stage(smem_base, nxt % STAGES, nxt, m0, n0); CP_COMMIT(); }

        const uint32_t a_base = smem_base + SM_A(s);
        const uint32_t b_base = smem_base + SM_B(s);

        #pragma unroll
        for (int kk = 0; kk < 4; kk++) {          // 4 x k16 per BK=64
            const int k0 = kk * 16;
            uint32_t af[2][4];
            #pragma unroll
            for (int mt = 0; mt < 2; mt++) {
                uint32_t off = (wm * 32 + mt * 16 + a_row_b) * 128 + (k0 + a_kh) * 2;
                LDSM_X4(af[mt][0], af[mt][1], af[mt][2], af[mt][3],
                        a_base + SW128(off));
            }
            uint32_t bf[8][2];
            #pragma unroll
            for (int p = 0; p < 4; p++) {
                uint32_t off = (wn * 64 + p * 16 + b_row_b) * 128 + (k0 + b_kh) * 2;
                LDSM_X4(bf[2 * p][0], bf[2 * p][1], bf[2 * p + 1][0], bf[2 * p + 1][1],
                        b_base + SW128(off));
            }
            #pragma unroll
            for (int mt = 0; mt < 2; mt++)
                #pragma unroll
                for (int nt = 0; nt < 8; nt++)
                    MMA16816(acc[mt][nt], af[mt], bf[nt]);
        }
    }

    // epilogue: streaming stores
    const int er = lane >> 2;
    const int ec = (lane & 3) * 2;
    #pragma unroll
    for (int nt = 0; nt < 8; nt++) {
        const int n = n0 + wn * 64 + nt * 8 + ec;
        const float2 bv = *(const float2*)(bias + n);
        #pragma unroll
        for (int mt = 0; mt < 2; mt++) {
            const int m = m0 + wm * 32 + mt * 16 + er;
            float2 v0 = { acc[mt][nt][0] + bv.x, acc[mt][nt][1] + bv.y };
            float2 v1 = { acc[mt][nt][2] + bv.x, acc[mt][nt][3] + bv.y };
            stcs_f2(out + (size_t)m * N_DIM + n, v0);
            stcs_f2(out + (size_t)(m + 8) * N_DIM + n, v1);
        }
    }
}

// ================= launch =================
extern "C" void kernel_launch(void* const* d_in, const int* in_sizes, int n_in,
                              void* d_out, int out_size)
{
    const float* x            = (const float*)d_in[0];
    const int*   nvfp4_idx    = (const int*)d_in[1];
    const float* nvfp4_scales = (const float*)d_in[2];
    const float* nvfp4_gscale = (const float*)d_in[3];
    const float* w_fp8        = (const float*)d_in[4];
    const float* fp8_scale    = (const float*)d_in[5];
    const float* w_fp16       = (const float*)d_in[6];
    const float* bias         = (const float*)d_in[7];
    const void*  inv_perm     = (const void*)d_in[8];
    float*       out          = (float*)d_out;

    cudaFuncSetAttribute(gemm_hmma_kernel, cudaFuncAttributeMaxDynamicSharedMemorySize, SMEM_TOTAL);

    prep_kernel<<<XCONV_BLOCKS + N_DIM, 256>>>(x, nvfp4_idx, nvfp4_scales, nvfp4_gscale,
                                               w_fp8, fp8_scale, w_fp16, inv_perm);

    dim3 grid(N_DIM / BN, M_DIM / BM);   // (32, 32)
    gemm_hmma_kernel<<<grid, NTHREADS, SMEM_TOTAL>>>(bias, out);
}